// round 1
// baseline (speedup 1.0000x reference)
#include <cuda_runtime.h>
#include <cstdint>

#define HID  512
#define BATCH 4
#define SEQ  4096

// Scratch (static device globals; allocation-free per harness rules)
__device__ float g_qkv[(size_t)3 * BATCH * SEQ * HID];          // 96 MB: q | k | v
__device__ float g_scores[(size_t)BATCH * SEQ * SEQ];           // 256 MB

// ---------------------------------------------------------------------------
// tf32 helpers
// ---------------------------------------------------------------------------
__device__ __forceinline__ uint32_t f2tf32(float f) {
    uint32_t r;
    asm("cvt.rna.tf32.f32 %0, %1;" : "=r"(r) : "f"(f));
    return r;
}

__device__ __forceinline__ void mma8(float c[4],
                                     uint32_t a0, uint32_t a1, uint32_t a2, uint32_t a3,
                                     uint32_t b0, uint32_t b1) {
    asm volatile(
        "mma.sync.aligned.m16n8k8.row.col.f32.tf32.tf32.f32 "
        "{%0,%1,%2,%3}, {%4,%5,%6,%7}, {%8,%9}, {%0,%1,%2,%3};\n"
        : "+f"(c[0]), "+f"(c[1]), "+f"(c[2]), "+f"(c[3])
        : "r"(a0), "r"(a1), "r"(a2), "r"(a3), "r"(b0), "r"(b1));
}

// Split a float into tf32 hi + tf32 lo (3xtf32 trick -> ~fp32 accuracy)
__device__ __forceinline__ void split4(const float4 v, uint4& hi, uint4& lo) {
    uint32_t hx = f2tf32(v.x), hy = f2tf32(v.y), hz = f2tf32(v.z), hw = f2tf32(v.w);
    hi = make_uint4(hx, hy, hz, hw);
    lo = make_uint4(f2tf32(v.x - __uint_as_float(hx)),
                    f2tf32(v.y - __uint_as_float(hy)),
                    f2tf32(v.z - __uint_as_float(hz)),
                    f2tf32(v.w - __uint_as_float(hw)));
}

// ---------------------------------------------------------------------------
// GEMM NT:  C[m,n] = sum_k A[m,k] * B[n,k]   (both operands K-major)
// Tiles: BM=64, BN=64, BK=16. 128 threads (2x2 warps, each 32x32).
// Used for QKV projections (y = x W^T) and for S = Q K^T.
// ---------------------------------------------------------------------------
__global__ void __launch_bounds__(128) gemm_nt(
    const float* __restrict__ A, const float* __restrict__ B, float* __restrict__ C,
    int lda, int ldb, int ldc, int Kdim,
    long long sA_, long long sB_, long long sC_)
{
    __shared__ __align__(16) uint32_t sAhi[64][20], sAlo[64][20];
    __shared__ __align__(16) uint32_t sBhi[64][20], sBlo[64][20];

    const float* Ag = A + (long long)blockIdx.z * sA_ + (long long)blockIdx.y * 64 * lda;
    const float* Bg = B + (long long)blockIdx.z * sB_ + (long long)blockIdx.x * 64 * ldb;
    float*       Cg = C + (long long)blockIdx.z * sC_ + (long long)blockIdx.y * 64 * ldc
                        + (long long)blockIdx.x * 64;

    const int tid  = threadIdx.x;
    const int warp = tid >> 5, lane = tid & 31;
    const int wm = (warp >> 1) * 32, wn = (warp & 1) * 32;
    const int lr = lane >> 2, lc = lane & 3;

    float acc[2][4][4] = {};

    for (int k0 = 0; k0 < Kdim; k0 += 16) {
        // stage gmem -> regs
        float4 va[2], vb[2];
        int r[2], c4[2];
#pragma unroll
        for (int i = 0; i < 2; i++) {
            int idx = tid + i * 128;              // 0..255
            r[i]  = idx >> 2;
            c4[i] = (idx & 3) * 4;
            va[i] = *(const float4*)(Ag + (long long)r[i] * lda + k0 + c4[i]);
            vb[i] = *(const float4*)(Bg + (long long)r[i] * ldb + k0 + c4[i]);
        }
        __syncthreads();
#pragma unroll
        for (int i = 0; i < 2; i++) {
            uint4 hi, lo;
            split4(va[i], hi, lo);
            *(uint4*)&sAhi[r[i]][c4[i]] = hi;
            *(uint4*)&sAlo[r[i]][c4[i]] = lo;
            split4(vb[i], hi, lo);
            *(uint4*)&sBhi[r[i]][c4[i]] = hi;
            *(uint4*)&sBlo[r[i]][c4[i]] = lo;
        }
        __syncthreads();

#pragma unroll
        for (int ks = 0; ks < 16; ks += 8) {
            uint32_t ah[2][4], al[2][4];
#pragma unroll
            for (int mi = 0; mi < 2; mi++) {
                int r0 = wm + mi * 16 + lr;
                ah[mi][0] = sAhi[r0    ][ks + lc    ];  al[mi][0] = sAlo[r0    ][ks + lc    ];
                ah[mi][1] = sAhi[r0 + 8][ks + lc    ];  al[mi][1] = sAlo[r0 + 8][ks + lc    ];
                ah[mi][2] = sAhi[r0    ][ks + lc + 4];  al[mi][2] = sAlo[r0    ][ks + lc + 4];
                ah[mi][3] = sAhi[r0 + 8][ks + lc + 4];  al[mi][3] = sAlo[r0 + 8][ks + lc + 4];
            }
#pragma unroll
            for (int ni = 0; ni < 4; ni++) {
                int n0 = wn + ni * 8 + lr;
                uint32_t bh0 = sBhi[n0][ks + lc], bh1 = sBhi[n0][ks + lc + 4];
                uint32_t bl0 = sBlo[n0][ks + lc], bl1 = sBlo[n0][ks + lc + 4];
#pragma unroll
                for (int mi = 0; mi < 2; mi++) {
                    mma8(acc[mi][ni], ah[mi][0], ah[mi][1], ah[mi][2], ah[mi][3], bh0, bh1);
                    mma8(acc[mi][ni], ah[mi][0], ah[mi][1], ah[mi][2], ah[mi][3], bl0, bl1);
                    mma8(acc[mi][ni], al[mi][0], al[mi][1], al[mi][2], al[mi][3], bh0, bh1);
                }
            }
        }
    }

#pragma unroll
    for (int mi = 0; mi < 2; mi++)
#pragma unroll
        for (int ni = 0; ni < 4; ni++) {
            int rr = wm + mi * 16 + lr;
            int cc = wn + ni * 8 + lc * 2;
            *(float2*)(Cg + (long long)rr * ldc + cc)       = make_float2(acc[mi][ni][0], acc[mi][ni][1]);
            *(float2*)(Cg + (long long)(rr + 8) * ldc + cc) = make_float2(acc[mi][ni][2], acc[mi][ni][3]);
        }
}

// ---------------------------------------------------------------------------
// GEMM NN:  C[m,n] = sum_k A[m,k] * B[k,n]   (B is N-contiguous)
// Used for O = P V.
// ---------------------------------------------------------------------------
__global__ void __launch_bounds__(128) gemm_nn(
    const float* __restrict__ A, const float* __restrict__ B, float* __restrict__ C,
    int lda, int ldb, int ldc, int Kdim,
    long long sA_, long long sB_, long long sC_)
{
    __shared__ __align__(16) uint32_t sAhi[64][20], sAlo[64][20];
    __shared__ __align__(16) uint32_t sBhi[16][68], sBlo[16][68];

    const float* Ag = A + (long long)blockIdx.z * sA_ + (long long)blockIdx.y * 64 * lda;
    const float* Bg = B + (long long)blockIdx.z * sB_ + (long long)blockIdx.x * 64;
    float*       Cg = C + (long long)blockIdx.z * sC_ + (long long)blockIdx.y * 64 * ldc
                        + (long long)blockIdx.x * 64;

    const int tid  = threadIdx.x;
    const int warp = tid >> 5, lane = tid & 31;
    const int wm = (warp >> 1) * 32, wn = (warp & 1) * 32;
    const int lr = lane >> 2, lc = lane & 3;

    float acc[2][4][4] = {};

    for (int k0 = 0; k0 < Kdim; k0 += 16) {
        float4 va[2], vb[2];
        int ra[2], ca4[2], rb[2], cb4[2];
#pragma unroll
        for (int i = 0; i < 2; i++) {
            int idx = tid + i * 128;
            ra[i]  = idx >> 2;
            ca4[i] = (idx & 3) * 4;
            va[i]  = *(const float4*)(Ag + (long long)ra[i] * lda + k0 + ca4[i]);
            rb[i]  = idx >> 4;                    // 0..15
            cb4[i] = (idx & 15) * 4;              // 0..60
            vb[i]  = *(const float4*)(Bg + (long long)(k0 + rb[i]) * ldb + cb4[i]);
        }
        __syncthreads();
#pragma unroll
        for (int i = 0; i < 2; i++) {
            uint4 hi, lo;
            split4(va[i], hi, lo);
            *(uint4*)&sAhi[ra[i]][ca4[i]] = hi;
            *(uint4*)&sAlo[ra[i]][ca4[i]] = lo;
            split4(vb[i], hi, lo);
            *(uint4*)&sBhi[rb[i]][cb4[i]] = hi;
            *(uint4*)&sBlo[rb[i]][cb4[i]] = lo;
        }
        __syncthreads();

#pragma unroll
        for (int ks = 0; ks < 16; ks += 8) {
            uint32_t ah[2][4], al[2][4];
#pragma unroll
            for (int mi = 0; mi < 2; mi++) {
                int r0 = wm + mi * 16 + lr;
                ah[mi][0] = sAhi[r0    ][ks + lc    ];  al[mi][0] = sAlo[r0    ][ks + lc    ];
                ah[mi][1] = sAhi[r0 + 8][ks + lc    ];  al[mi][1] = sAlo[r0 + 8][ks + lc    ];
                ah[mi][2] = sAhi[r0    ][ks + lc + 4];  al[mi][2] = sAlo[r0    ][ks + lc + 4];
                ah[mi][3] = sAhi[r0 + 8][ks + lc + 4];  al[mi][3] = sAlo[r0 + 8][ks + lc + 4];
            }
#pragma unroll
            for (int ni = 0; ni < 4; ni++) {
                int n0 = wn + ni * 8 + lr;
                uint32_t bh0 = sBhi[ks + lc    ][n0], bh1 = sBhi[ks + lc + 4][n0];
                uint32_t bl0 = sBlo[ks + lc    ][n0], bl1 = sBlo[ks + lc + 4][n0];
#pragma unroll
                for (int mi = 0; mi < 2; mi++) {
                    mma8(acc[mi][ni], ah[mi][0], ah[mi][1], ah[mi][2], ah[mi][3], bh0, bh1);
                    mma8(acc[mi][ni], ah[mi][0], ah[mi][1], ah[mi][2], ah[mi][3], bl0, bl1);
                    mma8(acc[mi][ni], al[mi][0], al[mi][1], al[mi][2], al[mi][3], bh0, bh1);
                }
            }
        }
    }

#pragma unroll
    for (int mi = 0; mi < 2; mi++)
#pragma unroll
        for (int ni = 0; ni < 4; ni++) {
            int rr = wm + mi * 16 + lr;
            int cc = wn + ni * 8 + lc * 2;
            *(float2*)(Cg + (long long)rr * ldc + cc)       = make_float2(acc[mi][ni][0], acc[mi][ni][1]);
            *(float2*)(Cg + (long long)(rr + 8) * ldc + cc) = make_float2(acc[mi][ni][2], acc[mi][ni][3]);
        }
}

// ---------------------------------------------------------------------------
// Row softmax over SEQ=4096, with /sqrt(H) scale folded in:
//   p_i = exp(scale*(s_i - max)) / sum
// One 256-thread block per row; 16 elements per thread held in registers.
// ---------------------------------------------------------------------------
__global__ void __launch_bounds__(256) softmax_kernel(float* __restrict__ S, float scale) {
    long long row = blockIdx.x;
    float* p = S + row * (long long)SEQ;
    const int tid = threadIdx.x;

    float4 v[4];
    float m = -3.4e38f;
#pragma unroll
    for (int i = 0; i < 4; i++) {
        v[i] = ((const float4*)p)[tid + i * 256];
        m = fmaxf(m, fmaxf(fmaxf(v[i].x, v[i].y), fmaxf(v[i].z, v[i].w)));
    }

    __shared__ float red[8];
#pragma unroll
    for (int o = 16; o; o >>= 1) m = fmaxf(m, __shfl_xor_sync(0xffffffffu, m, o));
    if ((tid & 31) == 0) red[tid >> 5] = m;
    __syncthreads();
    m = red[0];
#pragma unroll
    for (int i = 1; i < 8; i++) m = fmaxf(m, red[i]);

    float sum = 0.f;
#pragma unroll
    for (int i = 0; i < 4; i++) {
        v[i].x = __expf((v[i].x - m) * scale);
        v[i].y = __expf((v[i].y - m) * scale);
        v[i].z = __expf((v[i].z - m) * scale);
        v[i].w = __expf((v[i].w - m) * scale);
        sum += (v[i].x + v[i].y) + (v[i].z + v[i].w);
    }
#pragma unroll
    for (int o = 16; o; o >>= 1) sum += __shfl_xor_sync(0xffffffffu, sum, o);
    __syncthreads();                       // red reuse
    if ((tid & 31) == 0) red[tid >> 5] = sum;
    __syncthreads();
    float tot = 0.f;
#pragma unroll
    for (int i = 0; i < 8; i++) tot += red[i];
    float inv = 1.0f / tot;

#pragma unroll
    for (int i = 0; i < 4; i++) {
        v[i].x *= inv; v[i].y *= inv; v[i].z *= inv; v[i].w *= inv;
        ((float4*)p)[tid + i * 256] = v[i];
    }
}

// ---------------------------------------------------------------------------
// Launcher
// ---------------------------------------------------------------------------
extern "C" void kernel_launch(void* const* d_in, const int* in_sizes, int n_in,
                              void* d_out, int out_size) {
    const float* x  = (const float*)d_in[0];
    const float* Wq = (const float*)d_in[1];
    const float* Wk = (const float*)d_in[2];
    const float* Wv = (const float*)d_in[3];
    float* out = (float*)d_out;

    float *qp, *sp;
    cudaGetSymbolAddress((void**)&qp, g_qkv);
    cudaGetSymbolAddress((void**)&sp, g_scores);
    float* kp = qp + (long long)BATCH * SEQ * HID;
    float* vp = kp + (long long)BATCH * SEQ * HID;

    dim3 blk(128);

    // 1) QKV projections: y = x W^T   (M=16384, N=512, K=512)
    dim3 gq(HID / 64, (BATCH * SEQ) / 64, 1);
    gemm_nt<<<gq, blk>>>(x, Wq, qp, HID, HID, HID, HID, 0, 0, 0);
    gemm_nt<<<gq, blk>>>(x, Wk, kp, HID, HID, HID, HID, 0, 0, 0);
    gemm_nt<<<gq, blk>>>(x, Wv, vp, HID, HID, HID, HID, 0, 0, 0);

    // 2) S = Q K^T   (batched: M=N=4096, K=512)
    dim3 gs(SEQ / 64, SEQ / 64, BATCH);
    gemm_nt<<<gs, blk>>>(qp, kp, sp, HID, HID, SEQ, HID,
                         (long long)SEQ * HID, (long long)SEQ * HID, (long long)SEQ * SEQ);

    // 3) softmax rows with 1/sqrt(H) scale
    softmax_kernel<<<BATCH * SEQ, 256>>>(sp, 0.044194173824159216f);

    // 4) O = P V   (M=4096, N=512, K=4096, batched)
    dim3 gp(HID / 64, SEQ / 64, BATCH);
    gemm_nn<<<gp, blk>>>(sp, vp, out, SEQ, HID, HID, SEQ,
                         (long long)SEQ * SEQ, (long long)SEQ * HID, (long long)SEQ * HID);
}